// round 5
// baseline (speedup 1.0000x reference)
#include <cuda_runtime.h>

// PartialSum: out[b, p] = sum over 64 contiguous floats of x[b, p*64 : (p+1)*64]
// x: [2048, 65536] f32  -> out: [2048, 1024] f32 (2,097,152 partitions)
//
// Coalesced + MLP=8: each thread issues 8 independent LDG.128, each fully
// warp-coalesced (contiguous 512B per warp per load). 16 lanes per partition,
// 8 independent shfl_down reduction trees, writer lane stores 8 outputs.
// Block covers 2048 float4 = 8192 floats = 128 partitions.

__global__ void __launch_bounds__(256) partial_sum_kernel(
    const float4* __restrict__ x4, float* __restrict__ out)
{
    int t = threadIdx.x;
    int base = blockIdx.x * 2048 + t;              // float4 index of load 0

    float4 v[8];
    #pragma unroll
    for (int k = 0; k < 8; k++)
        v[k] = __ldg(&x4[base + k * 256]);

    float s[8];
    #pragma unroll
    for (int k = 0; k < 8; k++)
        s[k] = (v[k].x + v[k].y) + (v[k].z + v[k].w);

    // 8 independent 16-lane reduction trees (interleaved for ILP).
    #pragma unroll
    for (int off = 8; off > 0; off >>= 1) {
        #pragma unroll
        for (int k = 0; k < 8; k++)
            s[k] += __shfl_down_sync(0xffffffffu, s[k], off, 16);
    }

    if ((t & 15) == 0) {
        int p = blockIdx.x * 128 + (t >> 4);       // partition of load 0
        #pragma unroll
        for (int k = 0; k < 8; k++)
            out[p + k * 16] = s[k];
    }
}

extern "C" void kernel_launch(void* const* d_in, const int* in_sizes, int n_in,
                              void* d_out, int out_size)
{
    const float4* x4 = (const float4*)d_in[0];
    float* out = (float*)d_out;

    int blocks = out_size / 128;                   // 2,097,152 / 128 = 16384
    partial_sum_kernel<<<blocks, 256>>>(x4, out);
}